// round 8
// baseline (speedup 1.0000x reference)
#include <cuda_runtime.h>
#include <cuda_fp16.h>
#include <cuda_bf16.h>
#include <cstdint>

#define BHD 32       // B*H
#define SEQ 2048     // N
#define HD  64       // D
#define BM  128      // q rows per CTA (4 warps x 32 rows)
#define KT  64       // key tokens per tile
#define ST  72       // smem row stride in halves (conflict-free ldmatrix)
#define TILE_B (KT * ST * 2)                 // 9216 bytes per staged tile

#define OUT_ELEMS ((size_t)BHD * SEQ * HD)
#define TOT ((size_t)BHD * SEQ * HD)

__device__ float g_vsum[BHD * HD];
__device__ __align__(16) __nv_bfloat16 g_qc[TOT];   // bf16((2q-1)/128)
__device__ __align__(16) __nv_bfloat16 g_kc[TOT];   // bf16(2k-1)
__device__ __align__(16) half          g_vc[TOT];   // fp16(v)

// ---------------- pre-convert ----------------
__global__ __launch_bounds__(512)
void hd_convert_kernel(const float4* __restrict__ q, const float4* __restrict__ k,
                       const float4* __restrict__ v) {
    size_t i = (size_t)blockIdx.x * 512 + threadIdx.x;   // < TOT/4
    __nv_bfloat162* qo = (__nv_bfloat162*)g_qc;
    __nv_bfloat162* ko = (__nv_bfloat162*)g_kc;
    half2* vo = (half2*)g_vc;
    const float S = 0.0078125f;   // 1/128 folded into q (exact exponent shift in bf16)

    float4 xq = q[i];
    __nv_bfloat162 a, b;
    a.x = __float2bfloat16((2.f * xq.x - 1.f) * S); a.y = __float2bfloat16((2.f * xq.y - 1.f) * S);
    b.x = __float2bfloat16((2.f * xq.z - 1.f) * S); b.y = __float2bfloat16((2.f * xq.w - 1.f) * S);
    qo[2 * i] = a; qo[2 * i + 1] = b;

    float4 xk = k[i];
    a.x = __float2bfloat16(2.f * xk.x - 1.f); a.y = __float2bfloat16(2.f * xk.y - 1.f);
    b.x = __float2bfloat16(2.f * xk.z - 1.f); b.y = __float2bfloat16(2.f * xk.w - 1.f);
    ko[2 * i] = a; ko[2 * i + 1] = b;

    float4 xv = v[i];
    vo[2 * i]     = __floats2half2_rn(xv.x, xv.y);
    vo[2 * i + 1] = __floats2half2_rn(xv.z, xv.w);
}

// ---------------- vsum: per-(b,h) column sums of v ----------------
__global__ __launch_bounds__(1024)
void hd_vsum_kernel(const float* __restrict__ v) {
    __shared__ float red[16][64];
    int bh = blockIdx.x;
    int d = threadIdx.x & 63;
    int s = threadIdx.x >> 6;
    const float* vp = v + (size_t)bh * SEQ * HD + (size_t)s * 128 * HD + d;
    float acc = 0.f;
    #pragma unroll 8
    for (int t = 0; t < 128; ++t) acc += vp[t * HD];
    red[s][d] = acc;
    __syncthreads();
    if (threadIdx.x < 64) {
        float r = 0.f;
        #pragma unroll
        for (int i = 0; i < 16; ++i) r += red[i][threadIdx.x];
        g_vsum[bh * HD + threadIdx.x] = r;
    }
}

// ---------------- mma / ldmatrix / cp.async helpers ----------------
__device__ __forceinline__ void mma_bf16(float* c, const uint32_t a[4], uint32_t b0, uint32_t b1) {
    asm volatile(
        "mma.sync.aligned.m16n8k16.row.col.f32.bf16.bf16.f32 "
        "{%0,%1,%2,%3},{%4,%5,%6,%7},{%8,%9},{%0,%1,%2,%3};\n"
        : "+f"(c[0]), "+f"(c[1]), "+f"(c[2]), "+f"(c[3])
        : "r"(a[0]), "r"(a[1]), "r"(a[2]), "r"(a[3]), "r"(b0), "r"(b1));
}
__device__ __forceinline__ void mma_f16(float* c, const uint32_t a[4], uint32_t b0, uint32_t b1) {
    asm volatile(
        "mma.sync.aligned.m16n8k16.row.col.f32.f16.f16.f32 "
        "{%0,%1,%2,%3},{%4,%5,%6,%7},{%8,%9},{%0,%1,%2,%3};\n"
        : "+f"(c[0]), "+f"(c[1]), "+f"(c[2]), "+f"(c[3])
        : "r"(a[0]), "r"(a[1]), "r"(a[2]), "r"(a[3]), "r"(b0), "r"(b1));
}
__device__ __forceinline__ void ldsm_x4(uint32_t& r0, uint32_t& r1, uint32_t& r2, uint32_t& r3, uint32_t a) {
    asm volatile("ldmatrix.sync.aligned.m8n8.x4.shared.b16 {%0,%1,%2,%3}, [%4];\n"
        : "=r"(r0), "=r"(r1), "=r"(r2), "=r"(r3) : "r"(a));
}
__device__ __forceinline__ void ldsm_x4_t(uint32_t& r0, uint32_t& r1, uint32_t& r2, uint32_t& r3, uint32_t a) {
    asm volatile("ldmatrix.sync.aligned.m8n8.x4.trans.shared.b16 {%0,%1,%2,%3}, [%4];\n"
        : "=r"(r0), "=r"(r1), "=r"(r2), "=r"(r3) : "r"(a));
}
__device__ __forceinline__ uint32_t smem_u32(const void* p) {
    return (uint32_t)__cvta_generic_to_shared(p);
}
__device__ __forceinline__ uint32_t pack_h2(float a, float b) {
    __half2 h = __floats2half2_rn(a, b);
    return *(uint32_t*)&h;
}
__device__ __forceinline__ void cp16(uint32_t dst, const void* src) {
    asm volatile("cp.async.cg.shared.global [%0], [%1], 16;\n" :: "r"(dst), "l"(src));
}
__device__ __forceinline__ void cp_commit() {
    asm volatile("cp.async.commit_group;\n");
}
template<int N>
__device__ __forceinline__ void cp_wait() {
    asm volatile("cp.async.wait_group %0;\n" :: "n"(N));
}

// issue one 64x64 16-bit tile (rows of 128B) into smem (byte stride 144), 128 threads
__device__ __forceinline__ void issue_tile(uint32_t sdst, const void* gsrc, int tid) {
    #pragma unroll
    for (int i = 0; i < 4; ++i) {
        int idx = i * 128 + tid;
        int r = idx >> 3, c = idx & 7;
        cp16(sdst + (uint32_t)(r * (ST * 2) + c * 16), (const char*)gsrc + r * 128 + c * 16);
    }
}

__global__ __launch_bounds__(128, 4)
void hd_attn_kernel(float* __restrict__ outp) {
    __shared__ __align__(16) char pool[4 * TILE_B];   // 36864 B
    __shared__ float srs[BM];
    __shared__ float svs[HD];

    const int tid = threadIdx.x;
    const int w = tid >> 5;
    const int lane = tid & 31;
    const int g = lane >> 2;
    const int qd = lane & 3;
    const int group = lane >> 3;
    const int lr = lane & 7;
    const int bh = blockIdx.y;
    const int m0 = blockIdx.x * BM;
    const size_t base = (size_t)bh * SEQ * HD;

    const int krow = (group >> 1) * 8 + lr;
    const int kcol = (group & 1) * 8;
    const int vrow = (group & 1) * 8 + lr;
    const int vcol = (group >> 1) * 8;

    const uint32_t pb = smem_u32(pool);
    const __nv_bfloat16* kg = g_kc + base;
    const half* vg = g_vc + base;

    // ---- stage Q and consume to regs ----
    {
        const char* qg = (const char*)(g_qc + base + (size_t)m0 * HD);
        #pragma unroll
        for (int i = 0; i < 8; ++i) {
            int idx = i * 128 + tid;
            int r = idx >> 3, c = idx & 7;
            cp16(pb + (uint32_t)(r * (ST * 2) + c * 16), qg + r * 128 + c * 16);
        }
        cp_commit();
    }
    if (tid < HD) svs[tid] = g_vsum[bh * HD + tid];
    cp_wait<0>();
    __syncthreads();

    const int r1 = w * 32 + g;
    uint32_t aq[4][8];
    {
        const __nv_bfloat16* sq = (const __nv_bfloat16*)pool;
        #pragma unroll
        for (int j = 0; j < 4; ++j) {
            int k0 = j * 16 + qd * 2;
            aq[j][0] = *(const uint32_t*)&sq[r1 * ST + k0];
            aq[j][1] = *(const uint32_t*)&sq[(r1 + 8) * ST + k0];
            aq[j][2] = *(const uint32_t*)&sq[r1 * ST + k0 + 8];
            aq[j][3] = *(const uint32_t*)&sq[(r1 + 8) * ST + k0 + 8];
            aq[j][4] = *(const uint32_t*)&sq[(r1 + 16) * ST + k0];
            aq[j][5] = *(const uint32_t*)&sq[(r1 + 24) * ST + k0];
            aq[j][6] = *(const uint32_t*)&sq[(r1 + 16) * ST + k0 + 8];
            aq[j][7] = *(const uint32_t*)&sq[(r1 + 24) * ST + k0 + 8];
        }
    }
    __syncthreads();

    // ---------------- pass 1: row sums, depth-4 pipeline, 1 sync/iter ----------------
    #pragma unroll
    for (int t = 0; t < 3; ++t) {
        issue_tile(pb + t * TILE_B, kg + (size_t)t * KT * HD, tid);
        cp_commit();
    }

    float rs[4] = {0.f, 0.f, 0.f, 0.f};
    for (int kb = 0; kb < SEQ / KT; ++kb) {
        cp_wait<2>();           // tile kb resident
        __syncthreads();        // all warps done with tile kb-1 -> buffer (kb-1)&3 free
        if (kb + 3 < SEQ / KT)
            issue_tile(pb + ((kb + 3) & 3) * TILE_B, kg + (size_t)(kb + 3) * KT * HD, tid);
        cp_commit();

        const uint32_t sk_b = pb + (kb & 3) * TILE_B;
        #pragma unroll
        for (int tb = 0; tb < 4; ++tb) {
            float S2[2][2][4];
            #pragma unroll
            for (int blk = 0; blk < 2; ++blk)
                #pragma unroll
                for (int t = 0; t < 2; ++t)
                    { S2[blk][t][0]=0.f; S2[blk][t][1]=0.f; S2[blk][t][2]=0.f; S2[blk][t][3]=0.f; }
            #pragma unroll
            for (int j = 0; j < 4; ++j) {
                uint32_t b0, b1, b2, b3;
                ldsm_x4(b0, b1, b2, b3,
                        sk_b + 2u * (uint32_t)((tb * 16 + krow) * ST + j * 16 + kcol));
                mma_bf16(S2[0][0], &aq[j][0], b0, b1);
                mma_bf16(S2[0][1], &aq[j][0], b2, b3);
                mma_bf16(S2[1][0], &aq[j][4], b0, b1);
                mma_bf16(S2[1][1], &aq[j][4], b2, b3);
            }
            #pragma unroll
            for (int blk = 0; blk < 2; ++blk)
                #pragma unroll
                for (int t = 0; t < 2; ++t) {
                    rs[2*blk]   += __expf(S2[blk][t][0]) + __expf(S2[blk][t][1]);
                    rs[2*blk+1] += __expf(S2[blk][t][2]) + __expf(S2[blk][t][3]);
                }
        }
    }
    #pragma unroll
    for (int i = 0; i < 4; ++i) {
        rs[i] += __shfl_xor_sync(0xffffffffu, rs[i], 1);
        rs[i] += __shfl_xor_sync(0xffffffffu, rs[i], 2);
    }
    __syncthreads();            // pass-1 buffers fully consumed before pass-2 reuses pool
    if (qd == 0) {
        srs[r1] = rs[0]; srs[r1 + 8] = rs[1];
        srs[r1 + 16] = rs[2]; srs[r1 + 24] = rs[3];
    }
    __syncthreads();
    float inv[4];
    inv[0] = 1.f / srs[r1];      inv[1] = 1.f / srs[r1 + 8];
    inv[2] = 1.f / srs[r1 + 16]; inv[3] = 1.f / srs[r1 + 24];

    // ---------------- pass 2: depth-2 K+V pair pipeline, 1 sync/iter ----------------
    float O[2][8][4];
    #pragma unroll
    for (int blk = 0; blk < 2; ++blk)
        #pragma unroll
        for (int nb = 0; nb < 8; ++nb)
            { O[blk][nb][0]=0.f; O[blk][nb][1]=0.f; O[blk][nb][2]=0.f; O[blk][nb][3]=0.f; }

    float* scr = outp + OUT_ELEMS + (size_t)bh * SEQ * SEQ + (size_t)(m0 + r1) * SEQ;

    issue_tile(pb,              kg, tid);
    issue_tile(pb + 2 * TILE_B, vg, tid);
    cp_commit();

    for (int kb = 0; kb < SEQ / KT; ++kb) {
        cp_wait<0>();           // pair kb resident (only outstanding group)
        __syncthreads();        // all warps done with pair kb-1 -> its buffers free
        if (kb + 1 < SEQ / KT) {
            int nb1 = (kb + 1) & 1;
            issue_tile(pb + nb1 * TILE_B,       kg + (size_t)(kb + 1) * KT * HD, tid);
            issue_tile(pb + (2 + nb1) * TILE_B, vg + (size_t)(kb + 1) * KT * HD, tid);
        }
        cp_commit();

        const uint32_t sk_b  = pb + (kb & 1) * TILE_B;
        const uint32_t svh_b = pb + (2 + (kb & 1)) * TILE_B;

        #pragma unroll
        for (int tb = 0; tb < 4; ++tb) {
            // QK for this 16-token block
            float S2[2][2][4];
            #pragma unroll
            for (int blk = 0; blk < 2; ++blk)
                #pragma unroll
                for (int t = 0; t < 2; ++t)
                    { S2[blk][t][0]=0.f; S2[blk][t][1]=0.f; S2[blk][t][2]=0.f; S2[blk][t][3]=0.f; }
            #pragma unroll
            for (int j = 0; j < 4; ++j) {
                uint32_t b0, b1, b2, b3;
                ldsm_x4(b0, b1, b2, b3,
                        sk_b + 2u * (uint32_t)((tb * 16 + krow) * ST + j * 16 + kcol));
                mma_bf16(S2[0][0], &aq[j][0], b0, b1);
                mma_bf16(S2[0][1], &aq[j][0], b2, b3);
                mma_bf16(S2[1][0], &aq[j][4], b0, b1);
                mma_bf16(S2[1][1], &aq[j][4], b2, b3);
            }

            // exp, normalized score store, pack e = p-1 as fp16 A-fragments
            uint32_t ea[2][4];
            #pragma unroll
            for (int blk = 0; blk < 2; ++blk) {
                #pragma unroll
                for (int t = 0; t < 2; ++t) {
                    float p0 = __expf(S2[blk][t][0]);
                    float p1 = __expf(S2[blk][t][1]);
                    float p2 = __expf(S2[blk][t][2]);
                    float p3 = __expf(S2[blk][t][3]);
                    int col = kb * KT + tb * 16 + t * 8 + qd * 2;
                    size_t ro = (size_t)(blk * 16) * SEQ;
                    __stcs((float2*)&scr[ro + col],
                           make_float2(p0 * inv[2*blk], p1 * inv[2*blk]));
                    __stcs((float2*)&scr[ro + (size_t)8 * SEQ + col],
                           make_float2(p2 * inv[2*blk+1], p3 * inv[2*blk+1]));
                    ea[blk][t*2]   = pack_h2(p0 - 1.f, p1 - 1.f);
                    ea[blk][t*2+1] = pack_h2(p2 - 1.f, p3 - 1.f);
                }
            }

            // EV k-step for this 16-token block
            #pragma unroll
            for (int d2 = 0; d2 < 4; ++d2) {
                uint32_t b0, b1, b2, b3;
                ldsm_x4_t(b0, b1, b2, b3,
                          svh_b + 2u * (uint32_t)((tb * 16 + vrow) * ST + d2 * 16 + vcol));
                mma_f16(O[0][2*d2],   ea[0], b0, b1);
                mma_f16(O[0][2*d2+1], ea[0], b2, b3);
                mma_f16(O[1][2*d2],   ea[1], b0, b1);
                mma_f16(O[1][2*d2+1], ea[1], b2, b3);
            }
        }
    }

    // out = (vsum + O) / rowsum
    #pragma unroll
    for (int blk = 0; blk < 2; ++blk) {
        #pragma unroll
        for (int nb = 0; nb < 8; ++nb) {
            int d0 = nb * 8 + qd * 2;
            float vs0 = svs[d0], vs1 = svs[d0 + 1];
            float2 o0 = make_float2((O[blk][nb][0] + vs0) * inv[2*blk],
                                    (O[blk][nb][1] + vs1) * inv[2*blk]);
            float2 o1 = make_float2((O[blk][nb][2] + vs0) * inv[2*blk+1],
                                    (O[blk][nb][3] + vs1) * inv[2*blk+1]);
            int r = m0 + r1 + blk * 16;
            __stcs((float2*)&outp[base + (size_t)r * HD + d0], o0);
            __stcs((float2*)&outp[base + (size_t)(r + 8) * HD + d0], o1);
        }
    }
}

extern "C" void kernel_launch(void* const* d_in, const int* in_sizes, int n_in,
                              void* d_out, int out_size) {
    const float* q = (const float*)d_in[0];
    const float* k = (const float*)d_in[1];
    const float* v = (const float*)d_in[2];
    float* o = (float*)d_out;

    hd_convert_kernel<<<(int)(TOT / 4 / 512), 512>>>((const float4*)q, (const float4*)k,
                                                     (const float4*)v);
    hd_vsum_kernel<<<BHD, 1024>>>(v);
    dim3 grid(SEQ / BM, BHD);
    hd_attn_kernel<<<grid, 128>>>(o);
}

// round 9
// speedup vs baseline: 1.0823x; 1.0823x over previous
#include <cuda_runtime.h>
#include <cuda_fp16.h>
#include <cuda_bf16.h>
#include <cstdint>

#define BHD 32       // B*H
#define SEQ 2048     // N
#define HD  64       // D
#define BM  128      // q rows per CTA (4 warps x 32 rows)
#define KT  64       // key tokens per tile
#define NKT (SEQ / KT)        // 32 k-tiles total
#define KHALF (NKT / 2)       // 16 k-tiles per z-half
#define ST  72       // smem row stride in halves (conflict-free ldmatrix)
#define TILE_B (KT * ST * 2)  // 9216 bytes per staged tile

#define OUT_ELEMS ((size_t)BHD * SEQ * HD)
#define TOT ((size_t)BHD * SEQ * HD)

__device__ float g_vsum[BHD * HD];
__device__ float g_rsp[2 * BHD * SEQ];              // partial rowsums per z-half
__device__ __align__(16) float g_op[2 * TOT];       // partial O per z-half
__device__ __align__(16) __nv_bfloat16 g_qc[TOT];   // bf16((2q-1)/128)
__device__ __align__(16) __nv_bfloat16 g_kc[TOT];   // bf16(2k-1)
__device__ __align__(16) half          g_vc[TOT];   // fp16(v)

// ---------------- pre-convert ----------------
__global__ __launch_bounds__(512)
void hd_convert_kernel(const float4* __restrict__ q, const float4* __restrict__ k,
                       const float4* __restrict__ v) {
    size_t i = (size_t)blockIdx.x * 512 + threadIdx.x;   // < TOT/4
    __nv_bfloat162* qo = (__nv_bfloat162*)g_qc;
    __nv_bfloat162* ko = (__nv_bfloat162*)g_kc;
    half2* vo = (half2*)g_vc;
    const float S = 0.0078125f;   // 1/128 folded into q (exact exponent shift in bf16)

    float4 xq = q[i];
    __nv_bfloat162 a, b;
    a.x = __float2bfloat16((2.f * xq.x - 1.f) * S); a.y = __float2bfloat16((2.f * xq.y - 1.f) * S);
    b.x = __float2bfloat16((2.f * xq.z - 1.f) * S); b.y = __float2bfloat16((2.f * xq.w - 1.f) * S);
    qo[2 * i] = a; qo[2 * i + 1] = b;

    float4 xk = k[i];
    a.x = __float2bfloat16(2.f * xk.x - 1.f); a.y = __float2bfloat16(2.f * xk.y - 1.f);
    b.x = __float2bfloat16(2.f * xk.z - 1.f); b.y = __float2bfloat16(2.f * xk.w - 1.f);
    ko[2 * i] = a; ko[2 * i + 1] = b;

    float4 xv = v[i];
    vo[2 * i]     = __floats2half2_rn(xv.x, xv.y);
    vo[2 * i + 1] = __floats2half2_rn(xv.z, xv.w);
}

// ---------------- vsum: per-(b,h) column sums of v ----------------
__global__ __launch_bounds__(1024)
void hd_vsum_kernel(const float* __restrict__ v) {
    __shared__ float red[16][64];
    int bh = blockIdx.x;
    int d = threadIdx.x & 63;
    int s = threadIdx.x >> 6;
    const float* vp = v + (size_t)bh * SEQ * HD + (size_t)s * 128 * HD + d;
    float acc = 0.f;
    #pragma unroll 8
    for (int t = 0; t < 128; ++t) acc += vp[t * HD];
    red[s][d] = acc;
    __syncthreads();
    if (threadIdx.x < 64) {
        float r = 0.f;
        #pragma unroll
        for (int i = 0; i < 16; ++i) r += red[i][threadIdx.x];
        g_vsum[bh * HD + threadIdx.x] = r;
    }
}

// ---------------- mma / ldmatrix / cp.async helpers ----------------
__device__ __forceinline__ void mma_bf16(float* c, const uint32_t a[4], uint32_t b0, uint32_t b1) {
    asm volatile(
        "mma.sync.aligned.m16n8k16.row.col.f32.bf16.bf16.f32 "
        "{%0,%1,%2,%3},{%4,%5,%6,%7},{%8,%9},{%0,%1,%2,%3};\n"
        : "+f"(c[0]), "+f"(c[1]), "+f"(c[2]), "+f"(c[3])
        : "r"(a[0]), "r"(a[1]), "r"(a[2]), "r"(a[3]), "r"(b0), "r"(b1));
}
__device__ __forceinline__ void mma_f16(float* c, const uint32_t a[4], uint32_t b0, uint32_t b1) {
    asm volatile(
        "mma.sync.aligned.m16n8k16.row.col.f32.f16.f16.f32 "
        "{%0,%1,%2,%3},{%4,%5,%6,%7},{%8,%9},{%0,%1,%2,%3};\n"
        : "+f"(c[0]), "+f"(c[1]), "+f"(c[2]), "+f"(c[3])
        : "r"(a[0]), "r"(a[1]), "r"(a[2]), "r"(a[3]), "r"(b0), "r"(b1));
}
__device__ __forceinline__ void ldsm_x4(uint32_t& r0, uint32_t& r1, uint32_t& r2, uint32_t& r3, uint32_t a) {
    asm volatile("ldmatrix.sync.aligned.m8n8.x4.shared.b16 {%0,%1,%2,%3}, [%4];\n"
        : "=r"(r0), "=r"(r1), "=r"(r2), "=r"(r3) : "r"(a));
}
__device__ __forceinline__ void ldsm_x4_t(uint32_t& r0, uint32_t& r1, uint32_t& r2, uint32_t& r3, uint32_t a) {
    asm volatile("ldmatrix.sync.aligned.m8n8.x4.trans.shared.b16 {%0,%1,%2,%3}, [%4];\n"
        : "=r"(r0), "=r"(r1), "=r"(r2), "=r"(r3) : "r"(a));
}
__device__ __forceinline__ uint32_t smem_u32(const void* p) {
    return (uint32_t)__cvta_generic_to_shared(p);
}
__device__ __forceinline__ uint32_t pack_h2(float a, float b) {
    __half2 h = __floats2half2_rn(a, b);
    return *(uint32_t*)&h;
}
__device__ __forceinline__ void cp16(uint32_t dst, const void* src) {
    asm volatile("cp.async.cg.shared.global [%0], [%1], 16;\n" :: "r"(dst), "l"(src));
}
__device__ __forceinline__ void cp_commit() {
    asm volatile("cp.async.commit_group;\n");
}
template<int N>
__device__ __forceinline__ void cp_wait() {
    asm volatile("cp.async.wait_group %0;\n" :: "n"(N));
}

// issue one 64x64 16-bit tile (rows of 128B) into smem (byte stride 144), 128 threads
__device__ __forceinline__ void issue_tile(uint32_t sdst, const void* gsrc, int tid) {
    #pragma unroll
    for (int i = 0; i < 4; ++i) {
        int idx = i * 128 + tid;
        int r = idx >> 3, c = idx & 7;
        cp16(sdst + (uint32_t)(r * (ST * 2) + c * 16), (const char*)gsrc + r * 128 + c * 16);
    }
}

// stage Q tile (BM rows) into pool and load per-warp A-fragments
__device__ __forceinline__ void load_q_frags(const char* qg, uint32_t pb, const void* pool,
                                             int tid, int r1, int qd, uint32_t aq[4][8]) {
    #pragma unroll
    for (int i = 0; i < 8; ++i) {
        int idx = i * 128 + tid;
        int r = idx >> 3, c = idx & 7;
        cp16(pb + (uint32_t)(r * (ST * 2) + c * 16), qg + r * 128 + c * 16);
    }
    cp_commit();
    cp_wait<0>();
    __syncthreads();
    const __nv_bfloat16* sq = (const __nv_bfloat16*)pool;
    #pragma unroll
    for (int j = 0; j < 4; ++j) {
        int k0 = j * 16 + qd * 2;
        aq[j][0] = *(const uint32_t*)&sq[r1 * ST + k0];
        aq[j][1] = *(const uint32_t*)&sq[(r1 + 8) * ST + k0];
        aq[j][2] = *(const uint32_t*)&sq[r1 * ST + k0 + 8];
        aq[j][3] = *(const uint32_t*)&sq[(r1 + 8) * ST + k0 + 8];
        aq[j][4] = *(const uint32_t*)&sq[(r1 + 16) * ST + k0];
        aq[j][5] = *(const uint32_t*)&sq[(r1 + 24) * ST + k0];
        aq[j][6] = *(const uint32_t*)&sq[(r1 + 16) * ST + k0 + 8];
        aq[j][7] = *(const uint32_t*)&sq[(r1 + 24) * ST + k0 + 8];
    }
    __syncthreads();
}

// ---------------- pass 1: partial rowsums over a k-half ----------------
__global__ __launch_bounds__(128, 4)
void hd_pass1_kernel() {
    __shared__ __align__(16) char pool[4 * TILE_B];

    const int tid = threadIdx.x;
    const int w = tid >> 5;
    const int lane = tid & 31;
    const int g = lane >> 2;
    const int qd = lane & 3;
    const int group = lane >> 3;
    const int lr = lane & 7;
    const int bh = blockIdx.y;
    const int m0 = blockIdx.x * BM;
    const int z = blockIdx.z;
    const size_t base = (size_t)bh * SEQ * HD;

    const int krow = (group >> 1) * 8 + lr;
    const int kcol = (group & 1) * 8;

    const uint32_t pb = smem_u32(pool);
    const __nv_bfloat16* kg = g_kc + base + (size_t)z * KHALF * KT * HD;

    const int r1 = w * 32 + g;
    uint32_t aq[4][8];
    load_q_frags((const char*)(g_qc + base + (size_t)m0 * HD), pb, pool, tid, r1, qd, aq);

    #pragma unroll
    for (int t = 0; t < 3; ++t) {
        issue_tile(pb + t * TILE_B, kg + (size_t)t * KT * HD, tid);
        cp_commit();
    }

    float rs[4] = {0.f, 0.f, 0.f, 0.f};
    for (int kb = 0; kb < KHALF; ++kb) {
        cp_wait<2>();
        __syncthreads();
        if (kb + 3 < KHALF)
            issue_tile(pb + ((kb + 3) & 3) * TILE_B, kg + (size_t)(kb + 3) * KT * HD, tid);
        cp_commit();

        const uint32_t sk_b = pb + (kb & 3) * TILE_B;
        #pragma unroll
        for (int tb = 0; tb < 4; ++tb) {
            float S2[2][2][4];
            #pragma unroll
            for (int blk = 0; blk < 2; ++blk)
                #pragma unroll
                for (int t = 0; t < 2; ++t)
                    { S2[blk][t][0]=0.f; S2[blk][t][1]=0.f; S2[blk][t][2]=0.f; S2[blk][t][3]=0.f; }
            #pragma unroll
            for (int j = 0; j < 4; ++j) {
                uint32_t b0, b1, b2, b3;
                ldsm_x4(b0, b1, b2, b3,
                        sk_b + 2u * (uint32_t)((tb * 16 + krow) * ST + j * 16 + kcol));
                mma_bf16(S2[0][0], &aq[j][0], b0, b1);
                mma_bf16(S2[0][1], &aq[j][0], b2, b3);
                mma_bf16(S2[1][0], &aq[j][4], b0, b1);
                mma_bf16(S2[1][1], &aq[j][4], b2, b3);
            }
            #pragma unroll
            for (int blk = 0; blk < 2; ++blk)
                #pragma unroll
                for (int t = 0; t < 2; ++t) {
                    rs[2*blk]   += __expf(S2[blk][t][0]) + __expf(S2[blk][t][1]);
                    rs[2*blk+1] += __expf(S2[blk][t][2]) + __expf(S2[blk][t][3]);
                }
        }
    }
    #pragma unroll
    for (int i = 0; i < 4; ++i) {
        rs[i] += __shfl_xor_sync(0xffffffffu, rs[i], 1);
        rs[i] += __shfl_xor_sync(0xffffffffu, rs[i], 2);
    }
    if (qd == 0) {
        float* rp = g_rsp + (size_t)z * BHD * SEQ + (size_t)bh * SEQ + m0;
        rp[r1]      = rs[0];
        rp[r1 + 8]  = rs[1];
        rp[r1 + 16] = rs[2];
        rp[r1 + 24] = rs[3];
    }
}

// ---------------- pass 2: score writes + partial O over a k-half ----------------
__global__ __launch_bounds__(128, 3)
void hd_pass2_kernel(float* __restrict__ outp) {
    __shared__ __align__(16) char pool[4 * TILE_B];
    __shared__ float srs[BM];

    const int tid = threadIdx.x;
    const int w = tid >> 5;
    const int lane = tid & 31;
    const int g = lane >> 2;
    const int qd = lane & 3;
    const int group = lane >> 3;
    const int lr = lane & 7;
    const int bh = blockIdx.y;
    const int m0 = blockIdx.x * BM;
    const int z = blockIdx.z;
    const size_t base = (size_t)bh * SEQ * HD;

    const int krow = (group >> 1) * 8 + lr;
    const int kcol = (group & 1) * 8;
    const int vrow = (group & 1) * 8 + lr;
    const int vcol = (group >> 1) * 8;

    const uint32_t pb = smem_u32(pool);
    const __nv_bfloat16* kg = g_kc + base + (size_t)z * KHALF * KT * HD;
    const half* vg = g_vc + base + (size_t)z * KHALF * KT * HD;

    // combined inv rowsums
    if (tid < BM) {
        const float* rp = g_rsp + (size_t)bh * SEQ + m0 + tid;
        srs[tid] = 1.f / (rp[0] + rp[(size_t)BHD * SEQ]);
    }

    const int r1 = w * 32 + g;
    uint32_t aq[4][8];
    load_q_frags((const char*)(g_qc + base + (size_t)m0 * HD), pb, pool, tid, r1, qd, aq);

    float inv[4];
    inv[0] = srs[r1];      inv[1] = srs[r1 + 8];
    inv[2] = srs[r1 + 16]; inv[3] = srs[r1 + 24];

    float O[2][8][4];
    #pragma unroll
    for (int blk = 0; blk < 2; ++blk)
        #pragma unroll
        for (int nb = 0; nb < 8; ++nb)
            { O[blk][nb][0]=0.f; O[blk][nb][1]=0.f; O[blk][nb][2]=0.f; O[blk][nb][3]=0.f; }

    float* scr = outp + OUT_ELEMS + (size_t)bh * SEQ * SEQ + (size_t)(m0 + r1) * SEQ
               + (size_t)z * KHALF * KT;

    issue_tile(pb,              kg, tid);
    issue_tile(pb + 2 * TILE_B, vg, tid);
    cp_commit();

    for (int kb = 0; kb < KHALF; ++kb) {
        cp_wait<0>();
        __syncthreads();
        if (kb + 1 < KHALF) {
            int nb1 = (kb + 1) & 1;
            issue_tile(pb + nb1 * TILE_B,       kg + (size_t)(kb + 1) * KT * HD, tid);
            issue_tile(pb + (2 + nb1) * TILE_B, vg + (size_t)(kb + 1) * KT * HD, tid);
        }
        cp_commit();

        const uint32_t sk_b  = pb + (kb & 1) * TILE_B;
        const uint32_t svh_b = pb + (2 + (kb & 1)) * TILE_B;

        #pragma unroll
        for (int tb = 0; tb < 4; ++tb) {
            float S2[2][2][4];
            #pragma unroll
            for (int blk = 0; blk < 2; ++blk)
                #pragma unroll
                for (int t = 0; t < 2; ++t)
                    { S2[blk][t][0]=0.f; S2[blk][t][1]=0.f; S2[blk][t][2]=0.f; S2[blk][t][3]=0.f; }
            #pragma unroll
            for (int j = 0; j < 4; ++j) {
                uint32_t b0, b1, b2, b3;
                ldsm_x4(b0, b1, b2, b3,
                        sk_b + 2u * (uint32_t)((tb * 16 + krow) * ST + j * 16 + kcol));
                mma_bf16(S2[0][0], &aq[j][0], b0, b1);
                mma_bf16(S2[0][1], &aq[j][0], b2, b3);
                mma_bf16(S2[1][0], &aq[j][4], b0, b1);
                mma_bf16(S2[1][1], &aq[j][4], b2, b3);
            }

            uint32_t ea[2][4];
            #pragma unroll
            for (int blk = 0; blk < 2; ++blk) {
                #pragma unroll
                for (int t = 0; t < 2; ++t) {
                    float p0 = __expf(S2[blk][t][0]);
                    float p1 = __expf(S2[blk][t][1]);
                    float p2 = __expf(S2[blk][t][2]);
                    float p3 = __expf(S2[blk][t][3]);
                    int col = kb * KT + tb * 16 + t * 8 + qd * 2;
                    size_t ro = (size_t)(blk * 16) * SEQ;
                    __stcs((float2*)&scr[ro + col],
                           make_float2(p0 * inv[2*blk], p1 * inv[2*blk]));
                    __stcs((float2*)&scr[ro + (size_t)8 * SEQ + col],
                           make_float2(p2 * inv[2*blk+1], p3 * inv[2*blk+1]));
                    ea[blk][t*2]   = pack_h2(p0 - 1.f, p1 - 1.f);
                    ea[blk][t*2+1] = pack_h2(p2 - 1.f, p3 - 1.f);
                }
            }

            #pragma unroll
            for (int d2 = 0; d2 < 4; ++d2) {
                uint32_t b0, b1, b2, b3;
                ldsm_x4_t(b0, b1, b2, b3,
                          svh_b + 2u * (uint32_t)((tb * 16 + vrow) * ST + d2 * 16 + vcol));
                mma_f16(O[0][2*d2],   ea[0], b0, b1);
                mma_f16(O[0][2*d2+1], ea[0], b2, b3);
                mma_f16(O[1][2*d2],   ea[1], b0, b1);
                mma_f16(O[1][2*d2+1], ea[1], b2, b3);
            }
        }
    }

    // write raw partial O for this z-half
    float* op = g_op + (size_t)z * TOT + base;
    #pragma unroll
    for (int blk = 0; blk < 2; ++blk) {
        #pragma unroll
        for (int nb = 0; nb < 8; ++nb) {
            int d0 = nb * 8 + qd * 2;
            int r = m0 + r1 + blk * 16;
            *(float2*)&op[(size_t)r * HD + d0]       = make_float2(O[blk][nb][0], O[blk][nb][1]);
            *(float2*)&op[(size_t)(r + 8) * HD + d0] = make_float2(O[blk][nb][2], O[blk][nb][3]);
        }
    }
}

// ---------------- finalize: out = (vsum + op0 + op1) / rowsum ----------------
__global__ __launch_bounds__(256)
void hd_finalize_kernel(float* __restrict__ outp) {
    size_t i = (size_t)blockIdx.x * 256 + threadIdx.x;   // float4 index, < TOT/4
    const int D4 = HD / 4;
    int bh  = (int)(i / (SEQ * D4));
    int rem = (int)(i % (SEQ * D4));
    int row = rem / D4;
    int d4  = rem % D4;

    const float* rp = g_rsp + (size_t)bh * SEQ + row;
    float inv = 1.f / (rp[0] + rp[(size_t)BHD * SEQ]);

    float4 a  = ((const float4*)g_op)[i];
    float4 b  = ((const float4*)(g_op + TOT))[i];
    float4 vs = ((const float4*)g_vsum)[bh * D4 + d4];

    float4 o;
    o.x = (vs.x + a.x + b.x) * inv;
    o.y = (vs.y + a.y + b.y) * inv;
    o.z = (vs.z + a.z + b.z) * inv;
    o.w = (vs.w + a.w + b.w) * inv;
    ((float4*)outp)[i] = o;
}

extern "C" void kernel_launch(void* const* d_in, const int* in_sizes, int n_in,
                              void* d_out, int out_size) {
    const float* q = (const float*)d_in[0];
    const float* k = (const float*)d_in[1];
    const float* v = (const float*)d_in[2];
    float* o = (float*)d_out;

    hd_convert_kernel<<<(int)(TOT / 4 / 512), 512>>>((const float4*)q, (const float4*)k,
                                                     (const float4*)v);
    hd_vsum_kernel<<<BHD, 1024>>>(v);
    dim3 grid(SEQ / BM, BHD, 2);
    hd_pass1_kernel<<<grid, 128>>>();
    hd_pass2_kernel<<<grid, 128>>>(o);
    hd_finalize_kernel<<<(int)(TOT / 4 / 256), 256>>>(o);
}